// round 8
// baseline (speedup 1.0000x reference)
#include <cuda_runtime.h>
#include <cuda_bf16.h>
#include <math.h>

// ---------------------------------------------------------------------------
// MTCNN ONet forward, N=2048. Round 8: conv1 -> tf32 mma implicit GEMM.
//  K1: conv1+PReLU+pool(3,2,ceil)  48->23   TF32 MMA      -> g_B1
//  K2: conv2+PReLU+pool(3,2)       23->10   TF32 MMA      -> g_B2
//  K4: conv3+PReLU+pool(2,2)       10->4    3xTF32 MMA    -> g_B3
//  K6: conv4+PReLU+permute flatten 4x4->1152 fp32         -> g_B4
//  K7: fc5 GEMM+PReLU              3xTF32 MMA             -> g_B5
//  K8: heads -> d_out [b|c|a]
// ---------------------------------------------------------------------------

#define NIMG 2048

__device__ float g_B1[(size_t)NIMG * 32 * 23 * 23];
__device__ float g_B2[(size_t)NIMG * 64 * 10 * 10];
__device__ float g_B3[(size_t)NIMG * 64 * 4 * 4];
__device__ float g_B4[(size_t)NIMG * 1152];
__device__ float g_B5[(size_t)NIMG * 256];

#define NEG_INF (-1e30f)

__device__ __forceinline__ unsigned f2tf32(float f) {
    unsigned u;
    asm("cvt.rna.tf32.f32 %0, %1;" : "=r"(u) : "f"(f));
    return u;
}

__device__ __forceinline__ void mma_tf32(float c[4],
    unsigned a0, unsigned a1, unsigned a2, unsigned a3,
    unsigned b0, unsigned b1)
{
    asm volatile(
        "mma.sync.aligned.m16n8k8.row.col.f32.tf32.tf32.f32 "
        "{%0,%1,%2,%3}, {%4,%5,%6,%7}, {%8,%9}, {%0,%1,%2,%3};"
        : "+f"(c[0]), "+f"(c[1]), "+f"(c[2]), "+f"(c[3])
        : "r"(a0), "r"(a1), "r"(a2), "r"(a3), "r"(b0), "r"(b1));
}

// ---------------------------------------------------------------------------
// K1: conv1 + PReLU + pool1 via TF32 mma. Grid (NIMG, 4), 256 threads.
// Block = (image, 12-pooled-row... i.e. conv-row slab q*12..q*12+12).
// GEMM: M = 13*46=598 (pad 38 tiles), N = 32 oc, K = 27 (pad 32).
// smem: in [3][15][48] tf32, w [32][40] tf32 (stride 40 -> conflict-free),
// cv [32][13*48] fp32 for fused pool.
// ---------------------------------------------------------------------------
#define K1_IN 0
#define K1_W 2160
#define K1_OFFT 3440
#define K1_B 3472
#define K1_A 3504
#define K1_CV 3536
#define K1_SMEM_FLOATS (K1_CV + 32 * 624)   // 23504 floats = 94016 B

__global__ __launch_bounds__(256) void k1_conv1_pool(
    const float* __restrict__ x, const float* __restrict__ w,
    const float* __restrict__ bias, const float* __restrict__ alpha)
{
    extern __shared__ float sm1[];
    unsigned* u_in = (unsigned*)(sm1 + K1_IN);   // [3][15][48]
    unsigned* u_w  = (unsigned*)(sm1 + K1_W);    // [32][40]
    int* s_off     = (int*)(sm1 + K1_OFFT);
    float* s_b     = sm1 + K1_B;
    float* s_a     = sm1 + K1_A;
    float* s_cv    = sm1 + K1_CV;                // [32][624]

    const int n = blockIdx.x;
    const int q = blockIdx.y;        // conv-row slab
    const int r0 = q * 12;
    const int nrows = (q == 3) ? 10 : 13;
    const int mlim = nrows * 46;
    const int t = threadIdx.x;

    // stage input rows r0..r0+14 (zero-fill beyond row 47)
    for (int i = t; i < 2160; i += 256) {
        const int ic = i / 720;
        const int rem = i - ic * 720;
        const int rl = rem / 48;
        const int col = rem - rl * 48;
        const int grow = r0 + rl;
        float v = (grow < 48) ? x[(size_t)n * 6912 + ic * 2304 + grow * 48 + col] : 0.f;
        u_in[i] = f2tf32(v);
    }
    // stage weights k-major [k 32][oc 32], stride 40, zero-pad k>=27
    for (int i = t; i < 1024; i += 256) {
        const int k = i >> 5;
        const int oc = i & 31;
        float v = (k < 27) ? w[oc * 27 + k] : 0.f;
        u_w[k * 40 + oc] = f2tf32(v);
    }
    if (t < 32) {
        const int k = t;
        const int ic = k / 9;
        const int r = k - ic * 9;
        s_off[t] = (k < 27) ? (ic * 720 + (r / 3) * 48 + (r % 3)) : 0;
        s_b[t] = bias[t];
        s_a[t] = alpha[t];
    }
    __syncthreads();

    const int warp = t >> 5;
    const int lane = t & 31;
    const int g = lane >> 2;
    const int tq = lane & 3;

    // 5 m-tiles per warp: tile = warp + 8j (tile < 38)
    int rb[5][2];
#pragma unroll
    for (int j = 0; j < 5; j++) {
        const int tile = warp + 8 * j;
#pragma unroll
        for (int h = 0; h < 2; h++) {
            int m = tile * 16 + g + 8 * h;
            if (m > 607) m = 607;
            const int ry = m / 46;
            const int cx = m - ry * 46;
            rb[j][h] = ry * 48 + cx;   // ry<=13 within 15 staged rows
        }
    }

    float c[5][4][4];
#pragma unroll
    for (int j = 0; j < 5; j++)
#pragma unroll
        for (int nt = 0; nt < 4; nt++)
#pragma unroll
            for (int qq = 0; qq < 4; qq++) c[j][nt][qq] = 0.f;

#pragma unroll
    for (int kt = 0; kt < 4; kt++) {
        const int k0 = kt * 8 + tq;
        const int off0 = s_off[k0];
        const int off1 = s_off[k0 + 4];
        unsigned b0[4], b1[4];
        const unsigned* wb = u_w + k0 * 40 + g;
#pragma unroll
        for (int nt = 0; nt < 4; nt++) {
            b0[nt] = wb[nt * 8];
            b1[nt] = wb[4 * 40 + nt * 8];
        }
#pragma unroll
        for (int j = 0; j < 5; j++) {
            if (warp + 8 * j < 38) {
                const unsigned a0 = u_in[rb[j][0] + off0];
                const unsigned a1 = u_in[rb[j][1] + off0];
                const unsigned a2 = u_in[rb[j][0] + off1];
                const unsigned a3 = u_in[rb[j][1] + off1];
#pragma unroll
                for (int nt = 0; nt < 4; nt++)
                    mma_tf32(c[j][nt], a0, a1, a2, a3, b0[nt], b1[nt]);
            }
        }
    }
    __syncthreads();

    // epilogue: bias + PReLU -> s_cv[oc][ry*48+cx]
#pragma unroll
    for (int j = 0; j < 5; j++) {
        const int tile = warp + 8 * j;
        if (tile < 38) {
#pragma unroll
            for (int nt = 0; nt < 4; nt++) {
                const int oc0 = nt * 8 + 2 * tq;
                const int oc1 = oc0 + 1;
                const float b00 = s_b[oc0], a00 = s_a[oc0];
                const float b01 = s_b[oc1], a01 = s_a[oc1];
#pragma unroll
                for (int h = 0; h < 2; h++) {
                    const int m = tile * 16 + g + 8 * h;
                    if (m < mlim) {
                        const int ry = m / 46;
                        const int cx = m - ry * 46;
                        float v0 = c[j][nt][2 * h + 0] + b00;
                        float v1 = c[j][nt][2 * h + 1] + b01;
                        s_cv[oc0 * 624 + ry * 48 + cx] = v0 >= 0.f ? v0 : a00 * v0;
                        s_cv[oc1 * 624 + ry * 48 + cx] = v1 >= 0.f ? v1 : a01 * v1;
                    }
                }
            }
        }
    }
    __syncthreads();

    // pool(3,2,ceil): pooled rows q*6 .. q*6+5 (q=3: 18..22)
    for (int i = t; i < 4416; i += 256) {
        const int oc = i / 138;
        const int rem = i - oc * 138;
        const int pyl = rem / 23;
        const int px = rem - pyl * 23;
        const int py = q * 6 + pyl;
        if (py < 23) {
            float m = NEG_INF;
#pragma unroll
            for (int ky = 0; ky < 3; ky++) {
                int ryl = 2 * pyl + ky;
                if (ryl > nrows - 1) ryl = nrows - 1;
#pragma unroll
                for (int kx = 0; kx < 3; kx++) {
                    int cx = 2 * px + kx;
                    if (cx > 45) cx = 45;
                    m = fmaxf(m, s_cv[oc * 624 + ryl * 48 + cx]);
                }
            }
            g_B1[((size_t)n * 32 + oc) * 529 + py * 23 + px] = m;
        }
    }
}

// ---------------------------------------------------------------------------
// K2: conv2 + PReLU + pool2 via TF32 mma. One image/block, 448 threads.
// ---------------------------------------------------------------------------
#define K2_STW 72
#define K2_SIN_SZ 17728
#define K2_SW_OFF K2_SIN_SZ
#define K2_SW_SZ (288 * K2_STW)
#define K2_OFF_OFF (K2_SW_OFF + K2_SW_SZ)
#define K2_B_OFF (K2_OFF_OFF + 288)
#define K2_A_OFF (K2_B_OFF + 64)
#define K2_SMEM_FLOATS (K2_A_OFF + 64)
#define K2_CV_STRIDE 448

__global__ __launch_bounds__(448, 1) void k2_conv2_pool(
    const float* __restrict__ w, const float* __restrict__ bias,
    const float* __restrict__ alpha)
{
    extern __shared__ float sm2[];
    float* s_in = sm2;
    float* s_w  = sm2 + K2_SW_OFF;
    int*   s_off = (int*)(sm2 + K2_OFF_OFF);
    float* s_b  = sm2 + K2_B_OFF;
    float* s_a  = sm2 + K2_A_OFF;
    float* s_cv = sm2;

    const int n = blockIdx.x;
    const int t = threadIdx.x;

    {
        const float* src = g_B1 + (size_t)n * 16928;
        for (int i = t; i < 16928; i += 448) {
            const int ic = i / 529;
            const int r = i - ic * 529;
            const int y = r / 23;
            const int x = r - y * 23;
            ((unsigned*)s_in)[ic * 552 + y * 24 + x] = f2tf32(src[i]);
        }
        for (int i = t; i < 18432; i += 448) {
            const int oc = i / 288;
            const int k = i - oc * 288;
            ((unsigned*)s_w)[k * K2_STW + oc] = f2tf32(w[i]);
        }
        if (t < 288) {
            const int k = t;
            const int ic = k / 9;
            const int r = k - ic * 9;
            s_off[k] = ic * 552 + (r / 3) * 24 + (r % 3);
        }
        if (t < 64) {
            s_b[t] = bias[t];
            s_a[t] = alpha[t];
        }
    }
    __syncthreads();

    const int warp = t >> 5;
    const int lane = t & 31;
    const int g = lane >> 2;
    const int tq = lane & 3;

    int rb[2][2];
    int mrow[2][2];
#pragma unroll
    for (int mi = 0; mi < 2; mi++) {
        const int mt = 2 * warp + mi;
        int m0 = mt * 16 + g;
        int m1 = m0 + 8;
        mrow[mi][0] = m0; mrow[mi][1] = m1;
        int c0 = m0 > 440 ? 440 : m0;
        int c1 = m1 > 440 ? 440 : m1;
        rb[mi][0] = (c0 / 21) * 24 + (c0 % 21);
        rb[mi][1] = (c1 / 21) * 24 + (c1 % 21);
    }

    float c[2][8][4];
#pragma unroll
    for (int mi = 0; mi < 2; mi++)
#pragma unroll
        for (int nt = 0; nt < 8; nt++)
#pragma unroll
            for (int qq = 0; qq < 4; qq++) c[mi][nt][qq] = 0.f;

    const unsigned* u_in = (const unsigned*)s_in;
    const unsigned* u_w = (const unsigned*)s_w;

    for (int kt = 0; kt < 36; kt++) {
        const int k0 = kt * 8 + tq;
        const int off0 = s_off[k0];
        const int off1 = s_off[k0 + 4];

        unsigned b0[8], b1[8];
        const unsigned* wb = u_w + k0 * K2_STW + g;
#pragma unroll
        for (int nt = 0; nt < 8; nt++) {
            b0[nt] = wb[nt * 8];
            b1[nt] = wb[4 * K2_STW + nt * 8];
        }
#pragma unroll
        for (int mi = 0; mi < 2; mi++) {
            const unsigned a0 = u_in[rb[mi][0] + off0];
            const unsigned a1 = u_in[rb[mi][1] + off0];
            const unsigned a2 = u_in[rb[mi][0] + off1];
            const unsigned a3 = u_in[rb[mi][1] + off1];
#pragma unroll
            for (int nt = 0; nt < 8; nt++)
                mma_tf32(c[mi][nt], a0, a1, a2, a3, b0[nt], b1[nt]);
        }
    }
    __syncthreads();

#pragma unroll
    for (int mi = 0; mi < 2; mi++) {
#pragma unroll
        for (int nt = 0; nt < 8; nt++) {
            const int oc0 = nt * 8 + 2 * tq;
            const int oc1 = oc0 + 1;
            const float b00 = s_b[oc0], a00 = s_a[oc0];
            const float b01 = s_b[oc1], a01 = s_a[oc1];
#pragma unroll
            for (int h = 0; h < 2; h++) {
                const int m = mrow[mi][h];
                if (m < 441) {
                    float v0 = c[mi][nt][2 * h + 0] + b00;
                    float v1 = c[mi][nt][2 * h + 1] + b01;
                    s_cv[oc0 * K2_CV_STRIDE + m] = v0 >= 0.f ? v0 : a00 * v0;
                    s_cv[oc1 * K2_CV_STRIDE + m] = v1 >= 0.f ? v1 : a01 * v1;
                }
            }
        }
    }
    __syncthreads();

    float* ob = g_B2 + (size_t)n * 6400;
    for (int i = t; i < 6400; i += 448) {
        const int oc = i / 100;
        const int r = i - oc * 100;
        const int py = r / 10;
        const int px = r - py * 10;
        const float* base = s_cv + oc * K2_CV_STRIDE + (py * 2) * 21 + px * 2;
        float m = NEG_INF;
#pragma unroll
        for (int ky = 0; ky < 3; ky++)
#pragma unroll
            for (int kx = 0; kx < 3; kx++)
                m = fmaxf(m, base[ky * 21 + kx]);
        ob[i] = m;
    }
}

// ---------------------------------------------------------------------------
// K4: conv3 + PReLU + pool3 via 3xTF32 mma. 4 img/block, 256 thr, grid 512.
// ---------------------------------------------------------------------------
#define K4_INH 0
#define K4_INL 7680
#define K4_WH 15360
#define K4_WL 25728
#define K4_OFFT 36096
#define K4_BO 36240
#define K4_AO 36304
#define K4_SMEM_FLOATS 36368

__global__ __launch_bounds__(256, 1) void k4_conv3_pool(
    const float* __restrict__ w, const float* __restrict__ bias,
    const float* __restrict__ alpha)
{
    extern __shared__ float sm4[];
    unsigned* inh = (unsigned*)(sm4 + K4_INH);
    unsigned* inl = (unsigned*)(sm4 + K4_INL);
    unsigned* wh  = (unsigned*)(sm4 + K4_WH);
    unsigned* wl  = (unsigned*)(sm4 + K4_WL);
    int* s_off    = (int*)(sm4 + K4_OFFT);
    float* s_b    = sm4 + K4_BO;
    float* s_a    = sm4 + K4_AO;
    float* s_cv   = sm4;

    const int n0 = blockIdx.x * 4;
    const int t = threadIdx.x;
    const int warp = t >> 5;
    const int lane = t & 31;
    const int g = lane >> 2;
    const int tq = lane & 3;

    if (t < 64) {
        s_b[t] = bias[t];
        s_a[t] = alpha[t];
    }
    if (t < 144) {
        const int ic = t / 9;
        const int r = t - ic * 9;
        s_off[t] = ic * 120 + (r / 3) * 12 + (r % 3);
    }

    int rb[2][2];
#pragma unroll
    for (int mi = 0; mi < 2; mi++) {
        const int mt = 2 * warp + mi;
#pragma unroll
        for (int h = 0; h < 2; h++) {
            const int m = mt * 16 + g + 8 * h;
            const int img = m >> 6;
            const int px = m & 63;
            rb[mi][h] = img * 1920 + (px >> 3) * 12 + (px & 7);
        }
    }

    float c[2][8][4];
#pragma unroll
    for (int mi = 0; mi < 2; mi++)
#pragma unroll
        for (int nt = 0; nt < 8; nt++)
#pragma unroll
            for (int qq = 0; qq < 4; qq++) c[mi][nt][qq] = 0.f;

    for (int chunk = 0; chunk < 4; chunk++) {
        __syncthreads();
        for (int i = t; i < 6400; i += 256) {
            const int im = i / 1600;
            const int rem = i - im * 1600;
            const int icl = rem / 100;
            const int r2 = rem - icl * 100;
            const int y = r2 / 10;
            const int xx = r2 - y * 10;
            const float f = g_B2[(size_t)(n0 + im) * 6400 + (chunk * 16 + icl) * 100 + r2];
            const unsigned hb = f2tf32(f);
            const unsigned lb = f2tf32(f - __uint_as_float(hb));
            const int di = im * 1920 + icl * 120 + y * 12 + xx;
            inh[di] = hb;
            inl[di] = lb;
        }
        for (int i = t; i < 9216; i += 256) {
            const int oc = i / 144;
            const int k = i - oc * 144;
            const float f = w[oc * 576 + chunk * 144 + k];
            const unsigned hb = f2tf32(f);
            const unsigned lb = f2tf32(f - __uint_as_float(hb));
            wh[k * 72 + oc] = hb;
            wl[k * 72 + oc] = lb;
        }
        __syncthreads();

        for (int kt = 0; kt < 18; kt++) {
            const int k0 = kt * 8 + tq;
            const int off0 = s_off[k0];
            const int off1 = s_off[k0 + 4];

            unsigned bh0[8], bh1[8], bl0[8], bl1[8];
            const unsigned* wbh = wh + k0 * 72 + g;
            const unsigned* wbl = wl + k0 * 72 + g;
#pragma unroll
            for (int nt = 0; nt < 8; nt++) {
                bh0[nt] = wbh[nt * 8];
                bh1[nt] = wbh[4 * 72 + nt * 8];
                bl0[nt] = wbl[nt * 8];
                bl1[nt] = wbl[4 * 72 + nt * 8];
            }
#pragma unroll
            for (int mi = 0; mi < 2; mi++) {
                const unsigned ah0 = inh[rb[mi][0] + off0];
                const unsigned ah1 = inh[rb[mi][1] + off0];
                const unsigned ah2 = inh[rb[mi][0] + off1];
                const unsigned ah3 = inh[rb[mi][1] + off1];
                const unsigned al0 = inl[rb[mi][0] + off0];
                const unsigned al1 = inl[rb[mi][1] + off0];
                const unsigned al2 = inl[rb[mi][0] + off1];
                const unsigned al3 = inl[rb[mi][1] + off1];
#pragma unroll
                for (int nt = 0; nt < 8; nt++) {
                    mma_tf32(c[mi][nt], ah0, ah1, ah2, ah3, bh0[nt], bh1[nt]);
                    mma_tf32(c[mi][nt], ah0, ah1, ah2, ah3, bl0[nt], bl1[nt]);
                    mma_tf32(c[mi][nt], al0, al1, al2, al3, bh0[nt], bh1[nt]);
                }
            }
        }
    }
    __syncthreads();

#pragma unroll
    for (int mi = 0; mi < 2; mi++) {
        const int mt = 2 * warp + mi;
#pragma unroll
        for (int nt = 0; nt < 8; nt++) {
            const int oc0 = nt * 8 + 2 * tq;
            const int oc1 = oc0 + 1;
            const float b00 = s_b[oc0], a00 = s_a[oc0];
            const float b01 = s_b[oc1], a01 = s_a[oc1];
#pragma unroll
            for (int h = 0; h < 2; h++) {
                const int m = mt * 16 + g + 8 * h;
                const int img = m >> 6;
                const int px = m & 63;
                float v0 = c[mi][nt][2 * h + 0] + b00;
                float v1 = c[mi][nt][2 * h + 1] + b01;
                s_cv[(img * 64 + oc0) * 64 + px] = v0 >= 0.f ? v0 : a00 * v0;
                s_cv[(img * 64 + oc1) * 64 + px] = v1 >= 0.f ? v1 : a01 * v1;
            }
        }
    }
    __syncthreads();

    for (int i = t; i < 4096; i += 256) {
        const int img = i >> 10;
        const int rem = i & 1023;
        const int oc = rem >> 4;
        const int p = rem & 15;
        const int py = p >> 2;
        const int px = p & 3;
        const float* base = s_cv + (img * 64 + oc) * 64 + py * 16 + px * 2;
        float m = fmaxf(fmaxf(base[0], base[1]), fmaxf(base[8], base[9]));
        g_B3[((size_t)(n0 + img) * 64 + oc) * 16 + p] = m;
    }
}

// ---------------------------------------------------------------------------
// K6: conv4 (64->128,2x2)+PReLU+permute flatten. Grid (NIMG/8, 2). (fp32)
// ---------------------------------------------------------------------------
#define K6_SMEM_FLOATS (8192 + 16384 + 64 + 64)
__global__ __launch_bounds__(256, 2) void k6_conv4(
    const float* __restrict__ w, const float* __restrict__ bias,
    const float* __restrict__ alpha)
{
    extern __shared__ float sm6[];
    float* s_in = sm6;
    float* s_w  = sm6 + 8192;
    float* s_b  = s_w + 16384;
    float* s_a  = s_b + 64;

    const int n0 = blockIdx.x * 8;
    const int och = blockIdx.y;
    const int t = threadIdx.x;
    {
        const float4* src = (const float4*)g_B3 + (size_t)n0 * 256;
        float4* dst = (float4*)s_in;
        for (int i = t; i < 2048; i += 256) dst[i] = src[i];
        const float4* ws = (const float4*)(w + (size_t)och * 64 * 256);
        float4* wd = (float4*)s_w;
        for (int j = t; j < 4096; j += 256) {
            const int oc = j >> 6, ic = j & 63;
            wd[ic * 64 + oc] = ws[oc * 64 + ic];
        }
        if (t < 64) {
            s_b[t] = bias[och * 64 + t];
            s_a[t] = alpha[och * 64 + t];
        }
    }
    __syncthreads();

    const int img = t >> 5;
    const int ocp = t & 31;
    float acc[2][9];
#pragma unroll
    for (int p = 0; p < 2; p++)
#pragma unroll
        for (int i = 0; i < 9; i++) acc[p][i] = 0.f;

    for (int ic = 0; ic < 64; ic++) {
        const float* ib = s_in + img * 1024 + ic * 16;
        float xi[16];
#pragma unroll
        for (int qv = 0; qv < 4; qv++) {
            float4 xv = *(const float4*)(ib + qv * 4);
            xi[qv * 4 + 0] = xv.x; xi[qv * 4 + 1] = xv.y;
            xi[qv * 4 + 2] = xv.z; xi[qv * 4 + 3] = xv.w;
        }
        const float* wp = s_w + (ic * 64 + ocp * 2) * 4;
        float4 w0 = *(const float4*)wp;
        float4 w1 = *(const float4*)(wp + 4);
#pragma unroll
        for (int h = 0; h < 3; h++)
#pragma unroll
            for (int ww = 0; ww < 3; ww++) {
                const float x00 = xi[h * 4 + ww];
                const float x01 = xi[h * 4 + ww + 1];
                const float x10 = xi[(h + 1) * 4 + ww];
                const float x11 = xi[(h + 1) * 4 + ww + 1];
                acc[0][h * 3 + ww] += x00 * w0.x + x01 * w0.y + x10 * w0.z + x11 * w0.w;
                acc[1][h * 3 + ww] += x00 * w1.x + x01 * w1.y + x10 * w1.z + x11 * w1.w;
            }
    }

    float* ob = g_B4 + (size_t)(n0 + img) * 1152;
#pragma unroll
    for (int p = 0; p < 2; p++) {
        const int ocl = ocp * 2 + p;
        const int oc = och * 64 + ocl;
        const float b0 = s_b[ocl], al = s_a[ocl];
#pragma unroll
        for (int h = 0; h < 3; h++)
#pragma unroll
            for (int ww = 0; ww < 3; ww++) {
                float v = acc[p][h * 3 + ww] + b0;
                v = v >= 0.f ? v : al * v;
                ob[ww * 384 + h * 128 + oc] = v;
            }
    }
}

// ---------------------------------------------------------------------------
// K7: fc5 via 3xTF32 mma. Grid (32, 4), 256 thr. Tile 64x64, k-slab 32.
// ---------------------------------------------------------------------------
__global__ __launch_bounds__(256) void k7_fc5(
    const float* __restrict__ W, const float* __restrict__ bias,
    const float* __restrict__ alpha)
{
    __shared__ unsigned sAh[64 * 36], sAl[64 * 36];
    __shared__ unsigned sBh[64 * 36], sBl[64 * 36];

    const int t = threadIdx.x;
    const int bm = blockIdx.x, bn = blockIdx.y;
    const int warp = t >> 5;
    const int lane = t & 31;
    const int g = lane >> 2;
    const int tq = lane & 3;
    const int w_m = warp & 3;
    const int w_n = warp >> 2;

    float c[4][4];
#pragma unroll
    for (int nt = 0; nt < 4; nt++)
#pragma unroll
        for (int qq = 0; qq < 4; qq++) c[nt][qq] = 0.f;

    for (int slab = 0; slab < 36; slab++) {
        const int k0s = slab * 32;
        __syncthreads();
        for (int j = t; j < 512; j += 256) {
            const int m = j >> 3;
            const int kq = (j & 7) * 4;
            float4 v = *(const float4*)(g_B4 + (size_t)(bm * 64 + m) * 1152 + k0s + kq);
            float4 u = *(const float4*)(W + (size_t)(bn * 64 + m) * 1152 + k0s + kq);
            const float va[4] = {v.x, v.y, v.z, v.w};
            const float ua[4] = {u.x, u.y, u.z, u.w};
#pragma unroll
            for (int e = 0; e < 4; e++) {
                unsigned hb = f2tf32(va[e]);
                sAh[m * 36 + kq + e] = hb;
                sAl[m * 36 + kq + e] = f2tf32(va[e] - __uint_as_float(hb));
                unsigned hb2 = f2tf32(ua[e]);
                sBh[m * 36 + kq + e] = hb2;
                sBl[m * 36 + kq + e] = f2tf32(ua[e] - __uint_as_float(hb2));
            }
        }
        __syncthreads();

#pragma unroll
        for (int kt = 0; kt < 4; kt++) {
            const int kk = kt * 8 + tq;
            const int r0 = (w_m * 16 + g) * 36;
            const int r1 = (w_m * 16 + g + 8) * 36;
            const unsigned ah0 = sAh[r0 + kk];
            const unsigned ah1 = sAh[r1 + kk];
            const unsigned ah2 = sAh[r0 + kk + 4];
            const unsigned ah3 = sAh[r1 + kk + 4];
            const unsigned al0 = sAl[r0 + kk];
            const unsigned al1 = sAl[r1 + kk];
            const unsigned al2 = sAl[r0 + kk + 4];
            const unsigned al3 = sAl[r1 + kk + 4];
#pragma unroll
            for (int nt = 0; nt < 4; nt++) {
                const int nr = (w_n * 32 + nt * 8 + g) * 36;
                const unsigned bh0 = sBh[nr + kk];
                const unsigned bh1 = sBh[nr + kk + 4];
                const unsigned bl0 = sBl[nr + kk];
                const unsigned bl1 = sBl[nr + kk + 4];
                mma_tf32(c[nt], ah0, ah1, ah2, ah3, bh0, bh1);
                mma_tf32(c[nt], ah0, ah1, ah2, ah3, bl0, bl1);
                mma_tf32(c[nt], al0, al1, al2, al3, bh0, bh1);
            }
        }
    }

#pragma unroll
    for (int nt = 0; nt < 4; nt++) {
        const int o0 = bn * 64 + w_n * 32 + nt * 8 + 2 * tq;
        const int o1 = o0 + 1;
        const float bi0 = bias[o0], al0 = alpha[o0];
        const float bi1 = bias[o1], al1 = alpha[o1];
#pragma unroll
        for (int h = 0; h < 2; h++) {
            const int m = bm * 64 + w_m * 16 + g + 8 * h;
            float v0 = c[nt][2 * h + 0] + bi0;
            float v1 = c[nt][2 * h + 1] + bi1;
            g_B5[(size_t)m * 256 + o0] = v0 >= 0.f ? v0 : al0 * v0;
            g_B5[(size_t)m * 256 + o1] = v1 >= 0.f ? v1 : al1 * v1;
        }
    }
}

// ---------------------------------------------------------------------------
// K8: heads. One warp per image. out layout: [b: N*4 | c: N*10 | a: N*2]
// ---------------------------------------------------------------------------
__global__ __launch_bounds__(256) void k8_heads(
    const float* __restrict__ w1, const float* __restrict__ b1,
    const float* __restrict__ w2, const float* __restrict__ b2,
    const float* __restrict__ w3, const float* __restrict__ b3,
    float* __restrict__ out)
{
    const int warp = (blockIdx.x * 256 + threadIdx.x) >> 5;
    const int lane = threadIdx.x & 31;
    if (warp >= NIMG) return;
    const float* hv = g_B5 + (size_t)warp * 256;
    float hr[8];
#pragma unroll
    for (int j = 0; j < 8; j++) hr[j] = hv[lane + j * 32];

    auto dot = [&](const float* wrow) {
        float s = 0.f;
#pragma unroll
        for (int j = 0; j < 8; j++) s += hr[j] * wrow[lane + j * 32];
#pragma unroll
        for (int off = 16; off; off >>= 1) s += __shfl_xor_sync(0xffffffffu, s, off);
        return s;
    };

    float* out_b = out;
    float* out_c = out + (size_t)NIMG * 4;
    float* out_a = out + (size_t)NIMG * 14;

    float l0 = dot(w1) + b1[0];
    float l1 = dot(w1 + 256) + b1[1];
    float mx = fmaxf(l0, l1);
    float e0 = expf(l0 - mx), e1 = expf(l1 - mx);
    float inv = 1.f / (e0 + e1);
    if (lane == 0) {
        out_a[warp * 2 + 0] = e0 * inv;
        out_a[warp * 2 + 1] = e1 * inv;
    }
#pragma unroll
    for (int o = 0; o < 4; o++) {
        float v = dot(w2 + o * 256) + b2[o];
        if (lane == 0) out_b[warp * 4 + o] = v;
    }
#pragma unroll
    for (int o = 0; o < 10; o++) {
        float v = dot(w3 + o * 256) + b3[o];
        if (lane == 0) out_c[warp * 10 + o] = v;
    }
}

// ---------------------------------------------------------------------------
extern "C" void kernel_launch(void* const* d_in, const int* in_sizes, int n_in,
                              void* d_out, int out_size)
{
    const float* x    = (const float*)d_in[0];
    const float* c1w  = (const float*)d_in[1];
    const float* c1b  = (const float*)d_in[2];
    const float* a1   = (const float*)d_in[3];
    const float* c2w  = (const float*)d_in[4];
    const float* c2b  = (const float*)d_in[5];
    const float* a2   = (const float*)d_in[6];
    const float* c3w  = (const float*)d_in[7];
    const float* c3b  = (const float*)d_in[8];
    const float* a3   = (const float*)d_in[9];
    const float* c4w  = (const float*)d_in[10];
    const float* c4b  = (const float*)d_in[11];
    const float* a4   = (const float*)d_in[12];
    const float* d5w  = (const float*)d_in[13];
    const float* d5b  = (const float*)d_in[14];
    const float* a5   = (const float*)d_in[15];
    const float* d61w = (const float*)d_in[16];
    const float* d61b = (const float*)d_in[17];
    const float* d62w = (const float*)d_in[18];
    const float* d62b = (const float*)d_in[19];
    const float* d63w = (const float*)d_in[20];
    const float* d63b = (const float*)d_in[21];
    float* out = (float*)d_out;

    cudaFuncSetAttribute(k1_conv1_pool, cudaFuncAttributeMaxDynamicSharedMemorySize,
                         K1_SMEM_FLOATS * 4);
    cudaFuncSetAttribute(k2_conv2_pool, cudaFuncAttributeMaxDynamicSharedMemorySize,
                         K2_SMEM_FLOATS * 4);
    cudaFuncSetAttribute(k4_conv3_pool, cudaFuncAttributeMaxDynamicSharedMemorySize,
                         K4_SMEM_FLOATS * 4);
    cudaFuncSetAttribute(k6_conv4, cudaFuncAttributeMaxDynamicSharedMemorySize,
                         K6_SMEM_FLOATS * 4);

    k1_conv1_pool<<<dim3(NIMG, 4), 256, K1_SMEM_FLOATS * 4>>>(x, c1w, c1b, a1);
    k2_conv2_pool<<<NIMG, 448, K2_SMEM_FLOATS * 4>>>(c2w, c2b, a2);
    k4_conv3_pool<<<NIMG / 4, 256, K4_SMEM_FLOATS * 4>>>(c3w, c3b, a3);
    k6_conv4<<<dim3(NIMG / 8, 2), 256, K6_SMEM_FLOATS * 4>>>(c4w, c4b, a4);
    k7_fc5<<<dim3(32, 4), 256>>>(d5w, d5b, a5);
    k8_heads<<<(NIMG * 32) / 256, 256>>>(d61w, d61b, d62w, d62b, d63w, d63b, out);
}

// round 9
// speedup vs baseline: 1.4888x; 1.4888x over previous
#include <cuda_runtime.h>
#include <cuda_bf16.h>
#include <math.h>

// ---------------------------------------------------------------------------
// MTCNN ONet forward, N=2048. Round 9:
//  K1: conv1+PReLU+pool(3,2,ceil)  48->23   fp32 (reverted) -> g_B1
//  K2: conv2+PReLU+pool(3,2)       23->10   TF32 MMA        -> g_B2
//  K4: conv3+PReLU+pool(2,2)       10->4    TF32 MMA (1x)   -> g_B3
//  K6: conv4+PReLU+permute flatten 4x4->1152 TF32 MMA (1x)  -> g_B4
//  K7: fc5 GEMM+PReLU              3xTF32 MMA               -> g_B5
//  K8: heads -> d_out [b|c|a]
// ---------------------------------------------------------------------------

#define NIMG 2048

__device__ float g_B1[(size_t)NIMG * 32 * 23 * 23];
__device__ float g_B2[(size_t)NIMG * 64 * 10 * 10];
__device__ float g_B3[(size_t)NIMG * 64 * 4 * 4];
__device__ float g_B4[(size_t)NIMG * 1152];
__device__ float g_B5[(size_t)NIMG * 256];

#define NEG_INF (-1e30f)

__device__ __forceinline__ unsigned f2tf32(float f) {
    unsigned u;
    asm("cvt.rna.tf32.f32 %0, %1;" : "=r"(u) : "f"(f));
    return u;
}

__device__ __forceinline__ void mma_tf32(float c[4],
    unsigned a0, unsigned a1, unsigned a2, unsigned a3,
    unsigned b0, unsigned b1)
{
    asm volatile(
        "mma.sync.aligned.m16n8k8.row.col.f32.tf32.tf32.f32 "
        "{%0,%1,%2,%3}, {%4,%5,%6,%7}, {%8,%9}, {%0,%1,%2,%3};"
        : "+f"(c[0]), "+f"(c[1]), "+f"(c[2]), "+f"(c[3])
        : "r"(a0), "r"(a1), "r"(a2), "r"(a3), "r"(b0), "r"(b1));
}

// ---------------------------------------------------------------------------
// K1: conv1 + PReLU + pool1. Grid (NIMG, 4), 288 threads, 2 CTAs/SM. (fp32)
// ---------------------------------------------------------------------------
#define K1_SMEM_FLOATS (6912 + 16928 + 216 + 8 + 8)
__global__ __launch_bounds__(288, 2) void k1_conv1_pool(
    const float* __restrict__ x, const float* __restrict__ w,
    const float* __restrict__ bias, const float* __restrict__ alpha)
{
    extern __shared__ float sm1[];
    float* s_in = sm1;            // 3*48*48
    float* s_cv = sm1 + 6912;     // 8*46*46
    float* s_w  = s_cv + 16928;   // 8*27
    float* s_b  = s_w + 216;
    float* s_a  = s_b + 8;

    const int n = blockIdx.x;
    const int ocg = blockIdx.y;
    const int tid = threadIdx.x;
    {
        const float4* src = (const float4*)(x + (size_t)n * 6912);
        float4* dst = (float4*)s_in;
        for (int i = tid; i < 6912 / 4; i += 288) dst[i] = src[i];
        if (tid < 216) s_w[tid] = w[ocg * 216 + tid];
        if (tid < 8) {
            s_b[tid] = bias[ocg * 8 + tid];
            s_a[tid] = alpha[ocg * 8 + tid];
        }
    }
    __syncthreads();

    if (tid < 276) {
        const int y = tid / 6;
        const int xg = (tid % 6) * 8;

        float acc[8][8];
#pragma unroll
        for (int o = 0; o < 8; o++)
#pragma unroll
            for (int j = 0; j < 8; j++) acc[o][j] = 0.f;

#pragma unroll
        for (int ic = 0; ic < 3; ic++) {
#pragma unroll
            for (int ky = 0; ky < 3; ky++) {
                const float* row = s_in + ic * 2304 + (y + ky) * 48;
                float xi[10];
#pragma unroll
                for (int j = 0; j < 10; j++) {
                    int c = xg + j;
                    xi[j] = row[c > 47 ? 47 : c];
                }
#pragma unroll
                for (int o = 0; o < 8; o++) {
                    const float* wp = s_w + o * 27 + ic * 9 + ky * 3;
                    float w0 = wp[0], w1 = wp[1], w2 = wp[2];
#pragma unroll
                    for (int j = 0; j < 8; j++)
                        acc[o][j] += xi[j] * w0 + xi[j + 1] * w1 + xi[j + 2] * w2;
                }
            }
        }
#pragma unroll
        for (int o = 0; o < 8; o++) {
            const float b0 = s_b[o], al = s_a[o];
            float* orow = s_cv + o * 2116 + y * 46;
#pragma unroll
            for (int j = 0; j < 8; j++) {
                const int xx = xg + j;
                if (xx < 46) {
                    float v = acc[o][j] + b0;
                    orow[xx] = v >= 0.f ? v : al * v;
                }
            }
        }
    }
    __syncthreads();

    float* ob = g_B1 + ((size_t)n * 32 + ocg * 8) * 529;
    for (int i = tid; i < 8 * 529; i += 288) {
        const int o = i / 529;
        const int rem = i % 529;
        const int py = rem / 23;
        const int px = rem % 23;
        const float* base = s_cv + o * 2116;
        float m = NEG_INF;
#pragma unroll
        for (int ky = 0; ky < 3; ky++) {
            int cy = py * 2 + ky; cy = cy > 45 ? 45 : cy;
#pragma unroll
            for (int kx = 0; kx < 3; kx++) {
                int cx = px * 2 + kx; cx = cx > 45 ? 45 : cx;
                m = fmaxf(m, base[cy * 46 + cx]);
            }
        }
        ob[i] = m;
    }
}

// ---------------------------------------------------------------------------
// K2: conv2 + PReLU + pool2 via TF32 mma. One image/block, 448 threads.
// ---------------------------------------------------------------------------
#define K2_STW 72
#define K2_SIN_SZ 17728
#define K2_SW_OFF K2_SIN_SZ
#define K2_SW_SZ (288 * K2_STW)
#define K2_OFF_OFF (K2_SW_OFF + K2_SW_SZ)
#define K2_B_OFF (K2_OFF_OFF + 288)
#define K2_A_OFF (K2_B_OFF + 64)
#define K2_SMEM_FLOATS (K2_A_OFF + 64)
#define K2_CV_STRIDE 448

__global__ __launch_bounds__(448, 1) void k2_conv2_pool(
    const float* __restrict__ w, const float* __restrict__ bias,
    const float* __restrict__ alpha)
{
    extern __shared__ float sm2[];
    float* s_in = sm2;
    float* s_w  = sm2 + K2_SW_OFF;
    int*   s_off = (int*)(sm2 + K2_OFF_OFF);
    float* s_b  = sm2 + K2_B_OFF;
    float* s_a  = sm2 + K2_A_OFF;
    float* s_cv = sm2;

    const int n = blockIdx.x;
    const int t = threadIdx.x;

    {
        const float* src = g_B1 + (size_t)n * 16928;
        for (int i = t; i < 16928; i += 448) {
            const int ic = i / 529;
            const int r = i - ic * 529;
            const int y = r / 23;
            const int x = r - y * 23;
            ((unsigned*)s_in)[ic * 552 + y * 24 + x] = f2tf32(src[i]);
        }
        for (int i = t; i < 18432; i += 448) {
            const int oc = i / 288;
            const int k = i - oc * 288;
            ((unsigned*)s_w)[k * K2_STW + oc] = f2tf32(w[i]);
        }
        if (t < 288) {
            const int k = t;
            const int ic = k / 9;
            const int r = k - ic * 9;
            s_off[k] = ic * 552 + (r / 3) * 24 + (r % 3);
        }
        if (t < 64) {
            s_b[t] = bias[t];
            s_a[t] = alpha[t];
        }
    }
    __syncthreads();

    const int warp = t >> 5;
    const int lane = t & 31;
    const int g = lane >> 2;
    const int tq = lane & 3;

    int rb[2][2];
    int mrow[2][2];
#pragma unroll
    for (int mi = 0; mi < 2; mi++) {
        const int mt = 2 * warp + mi;
        int m0 = mt * 16 + g;
        int m1 = m0 + 8;
        mrow[mi][0] = m0; mrow[mi][1] = m1;
        int c0 = m0 > 440 ? 440 : m0;
        int c1 = m1 > 440 ? 440 : m1;
        rb[mi][0] = (c0 / 21) * 24 + (c0 % 21);
        rb[mi][1] = (c1 / 21) * 24 + (c1 % 21);
    }

    float c[2][8][4];
#pragma unroll
    for (int mi = 0; mi < 2; mi++)
#pragma unroll
        for (int nt = 0; nt < 8; nt++)
#pragma unroll
            for (int qq = 0; qq < 4; qq++) c[mi][nt][qq] = 0.f;

    const unsigned* u_in = (const unsigned*)s_in;
    const unsigned* u_w = (const unsigned*)s_w;

    for (int kt = 0; kt < 36; kt++) {
        const int k0 = kt * 8 + tq;
        const int off0 = s_off[k0];
        const int off1 = s_off[k0 + 4];

        unsigned b0[8], b1[8];
        const unsigned* wb = u_w + k0 * K2_STW + g;
#pragma unroll
        for (int nt = 0; nt < 8; nt++) {
            b0[nt] = wb[nt * 8];
            b1[nt] = wb[4 * K2_STW + nt * 8];
        }
#pragma unroll
        for (int mi = 0; mi < 2; mi++) {
            const unsigned a0 = u_in[rb[mi][0] + off0];
            const unsigned a1 = u_in[rb[mi][1] + off0];
            const unsigned a2 = u_in[rb[mi][0] + off1];
            const unsigned a3 = u_in[rb[mi][1] + off1];
#pragma unroll
            for (int nt = 0; nt < 8; nt++)
                mma_tf32(c[mi][nt], a0, a1, a2, a3, b0[nt], b1[nt]);
        }
    }
    __syncthreads();

#pragma unroll
    for (int mi = 0; mi < 2; mi++) {
#pragma unroll
        for (int nt = 0; nt < 8; nt++) {
            const int oc0 = nt * 8 + 2 * tq;
            const int oc1 = oc0 + 1;
            const float b00 = s_b[oc0], a00 = s_a[oc0];
            const float b01 = s_b[oc1], a01 = s_a[oc1];
#pragma unroll
            for (int h = 0; h < 2; h++) {
                const int m = mrow[mi][h];
                if (m < 441) {
                    float v0 = c[mi][nt][2 * h + 0] + b00;
                    float v1 = c[mi][nt][2 * h + 1] + b01;
                    s_cv[oc0 * K2_CV_STRIDE + m] = v0 >= 0.f ? v0 : a00 * v0;
                    s_cv[oc1 * K2_CV_STRIDE + m] = v1 >= 0.f ? v1 : a01 * v1;
                }
            }
        }
    }
    __syncthreads();

    float* ob = g_B2 + (size_t)n * 6400;
    for (int i = t; i < 6400; i += 448) {
        const int oc = i / 100;
        const int r = i - oc * 100;
        const int py = r / 10;
        const int px = r - py * 10;
        const float* base = s_cv + oc * K2_CV_STRIDE + (py * 2) * 21 + px * 2;
        float m = NEG_INF;
#pragma unroll
        for (int ky = 0; ky < 3; ky++)
#pragma unroll
            for (int kx = 0; kx < 3; kx++)
                m = fmaxf(m, base[ky * 21 + kx]);
        ob[i] = m;
    }
}

// ---------------------------------------------------------------------------
// K4: conv3 + PReLU + pool3 via single TF32 mma. 4 img/block, 256 thr.
// Implicit GEMM M=256 (4img x 8x8), N=64, K=576 in 4 ic-chunks of 144.
// ---------------------------------------------------------------------------
#define K4_INH 0
#define K4_WH 7680
#define K4_OFFT 18048
#define K4_BO 18192
#define K4_AO 18256
#define K4_SMEM_FLOATS 18320

__global__ __launch_bounds__(256) void k4_conv3_pool(
    const float* __restrict__ w, const float* __restrict__ bias,
    const float* __restrict__ alpha)
{
    extern __shared__ float sm4[];
    unsigned* inh = (unsigned*)(sm4 + K4_INH);   // [4img][16ic][10][12]
    unsigned* wh  = (unsigned*)(sm4 + K4_WH);    // [144][72]
    int* s_off    = (int*)(sm4 + K4_OFFT);       // [144]
    float* s_b    = sm4 + K4_BO;
    float* s_a    = sm4 + K4_AO;
    float* s_cv   = sm4;                         // overlay [4img][64oc][64px] = 16384

    const int n0 = blockIdx.x * 4;
    const int t = threadIdx.x;
    const int warp = t >> 5;
    const int lane = t & 31;
    const int g = lane >> 2;
    const int tq = lane & 3;

    if (t < 64) {
        s_b[t] = bias[t];
        s_a[t] = alpha[t];
    }
    if (t < 144) {
        const int ic = t / 9;
        const int r = t - ic * 9;
        s_off[t] = ic * 120 + (r / 3) * 12 + (r % 3);
    }

    int rb[2][2];
#pragma unroll
    for (int mi = 0; mi < 2; mi++) {
        const int mt = 2 * warp + mi;
#pragma unroll
        for (int h = 0; h < 2; h++) {
            const int m = mt * 16 + g + 8 * h;
            const int img = m >> 6;
            const int px = m & 63;
            rb[mi][h] = img * 1920 + (px >> 3) * 12 + (px & 7);
        }
    }

    float c[2][8][4];
#pragma unroll
    for (int mi = 0; mi < 2; mi++)
#pragma unroll
        for (int nt = 0; nt < 8; nt++)
#pragma unroll
            for (int qq = 0; qq < 4; qq++) c[mi][nt][qq] = 0.f;

    for (int chunk = 0; chunk < 4; chunk++) {
        __syncthreads();
        for (int i = t; i < 6400; i += 256) {
            const int im = i / 1600;
            const int rem = i - im * 1600;
            const int icl = rem / 100;
            const int r2 = rem - icl * 100;
            const int y = r2 / 10;
            const int xx = r2 - y * 10;
            inh[im * 1920 + icl * 120 + y * 12 + xx] =
                f2tf32(g_B2[(size_t)(n0 + im) * 6400 + (chunk * 16 + icl) * 100 + r2]);
        }
        for (int i = t; i < 9216; i += 256) {
            const int oc = i / 144;
            const int k = i - oc * 144;
            wh[k * 72 + oc] = f2tf32(w[oc * 576 + chunk * 144 + k]);
        }
        __syncthreads();

        for (int kt = 0; kt < 18; kt++) {
            const int k0 = kt * 8 + tq;
            const int off0 = s_off[k0];
            const int off1 = s_off[k0 + 4];

            unsigned b0[8], b1[8];
            const unsigned* wb = wh + k0 * 72 + g;
#pragma unroll
            for (int nt = 0; nt < 8; nt++) {
                b0[nt] = wb[nt * 8];
                b1[nt] = wb[4 * 72 + nt * 8];
            }
#pragma unroll
            for (int mi = 0; mi < 2; mi++) {
                const unsigned a0 = inh[rb[mi][0] + off0];
                const unsigned a1 = inh[rb[mi][1] + off0];
                const unsigned a2 = inh[rb[mi][0] + off1];
                const unsigned a3 = inh[rb[mi][1] + off1];
#pragma unroll
                for (int nt = 0; nt < 8; nt++)
                    mma_tf32(c[mi][nt], a0, a1, a2, a3, b0[nt], b1[nt]);
            }
        }
    }
    __syncthreads();

#pragma unroll
    for (int mi = 0; mi < 2; mi++) {
        const int mt = 2 * warp + mi;
#pragma unroll
        for (int nt = 0; nt < 8; nt++) {
            const int oc0 = nt * 8 + 2 * tq;
            const int oc1 = oc0 + 1;
            const float b00 = s_b[oc0], a00 = s_a[oc0];
            const float b01 = s_b[oc1], a01 = s_a[oc1];
#pragma unroll
            for (int h = 0; h < 2; h++) {
                const int m = mt * 16 + g + 8 * h;
                const int img = m >> 6;
                const int px = m & 63;
                float v0 = c[mi][nt][2 * h + 0] + b00;
                float v1 = c[mi][nt][2 * h + 1] + b01;
                s_cv[(img * 64 + oc0) * 64 + px] = v0 >= 0.f ? v0 : a00 * v0;
                s_cv[(img * 64 + oc1) * 64 + px] = v1 >= 0.f ? v1 : a01 * v1;
            }
        }
    }
    __syncthreads();

    for (int i = t; i < 4096; i += 256) {
        const int img = i >> 10;
        const int rem = i & 1023;
        const int oc = rem >> 4;
        const int p = rem & 15;
        const int py = p >> 2;
        const int px = p & 3;
        const float* base = s_cv + (img * 64 + oc) * 64 + py * 16 + px * 2;
        float m = fmaxf(fmaxf(base[0], base[1]), fmaxf(base[8], base[9]));
        g_B3[((size_t)(n0 + img) * 64 + oc) * 16 + p] = m;
    }
}

// ---------------------------------------------------------------------------
// K6: conv4 (64->128,2x2)+PReLU+permute flatten via single TF32 mma.
// 8 img/block, 320 threads (10 warps), grid NIMG/8 = 256.
// GEMM: M=72 (8img x 9 pos, pad 80 -> 5 m-tiles), N=128, K=256 in 2 chunks.
// Warp w: m-tile w>>1, n-half w&1 (8 n-tiles).
// smem: in [8img][32ic][16] tf32, w [128][136] tf32 (stride 136 = 8 mod 32).
// ---------------------------------------------------------------------------
#define K6_IN 0
#define K6_W 4096
#define K6_OFF 21504
#define K6_B 21632
#define K6_A 21760
#define K6_SMEM_FLOATS 21888

__global__ __launch_bounds__(320) void k6_conv4(
    const float* __restrict__ w, const float* __restrict__ bias,
    const float* __restrict__ alpha)
{
    extern __shared__ float sm6[];
    unsigned* u_in = (unsigned*)(sm6 + K6_IN);   // 4096: [8][32][16]
    unsigned* u_w  = (unsigned*)(sm6 + K6_W);    // 128*136 = 17408
    int* s_off     = (int*)(sm6 + K6_OFF);       // 128
    float* s_b     = sm6 + K6_B;                 // 128
    float* s_a     = sm6 + K6_A;                 // 128

    const int n0 = blockIdx.x * 8;
    const int t = threadIdx.x;
    const int warp = t >> 5;
    const int lane = t & 31;
    const int g = lane >> 2;
    const int tq = lane & 3;
    const int mt = warp >> 1;      // 0..4
    const int nh = warp & 1;       // n half

    if (t < 128) {
        const int k = t;
        const int icl = k >> 2;
        const int ky = (k >> 1) & 1;
        const int kx = k & 1;
        s_off[k] = icl * 16 + ky * 4 + kx;
        s_b[t] = bias[t];
        s_a[t] = alpha[t];
    }

    // A row bases (m -> img, pos), clamp pad rows to 71
    int rb[2];
#pragma unroll
    for (int h = 0; h < 2; h++) {
        int m = mt * 16 + g + 8 * h;
        if (m > 71) m = 71;
        const int im = m / 9;
        const int p = m - im * 9;
        rb[h] = im * 512 + (p / 3) * 4 + (p % 3);
    }

    float c[8][4];
#pragma unroll
    for (int nt = 0; nt < 8; nt++)
#pragma unroll
        for (int qq = 0; qq < 4; qq++) c[nt][qq] = 0.f;

    for (int chunk = 0; chunk < 2; chunk++) {
        __syncthreads();
        // stage input: [img][icl 32][16] for ic = chunk*32+icl
        for (int i = t; i < 4096; i += 320) {
            const int im = i >> 9;
            const int icl = (i >> 4) & 31;
            const int pos = i & 15;
            u_in[i] = f2tf32(g_B3[(size_t)(n0 + im) * 1024 + (chunk * 32 + icl) * 16 + pos]);
        }
        // stage weights k-major: u_w[k][oc], k = icl*4 + pos
        for (int i = t; i < 16384; i += 320) {
            const int k = i >> 7;
            const int oc = i & 127;
            u_w[k * 136 + oc] = f2tf32(w[oc * 256 + chunk * 128 + k]);
        }
        __syncthreads();

        for (int kt = 0; kt < 16; kt++) {
            const int k0 = kt * 8 + tq;
            const int off0 = s_off[k0];
            const int off1 = s_off[k0 + 4];

            unsigned b0[8], b1[8];
            const unsigned* wb = u_w + k0 * 136 + nh * 64 + g;
#pragma unroll
            for (int nt = 0; nt < 8; nt++) {
                b0[nt] = wb[nt * 8];
                b1[nt] = wb[4 * 136 + nt * 8];
            }
            const unsigned a0 = u_in[rb[0] + off0];
            const unsigned a1 = u_in[rb[1] + off0];
            const unsigned a2 = u_in[rb[0] + off1];
            const unsigned a3 = u_in[rb[1] + off1];
#pragma unroll
            for (int nt = 0; nt < 8; nt++)
                mma_tf32(c[nt], a0, a1, a2, a3, b0[nt], b1[nt]);
        }
    }

    // epilogue: bias + PReLU + permuted flatten write
#pragma unroll
    for (int nt = 0; nt < 8; nt++) {
        const int oc0 = nh * 64 + nt * 8 + 2 * tq;
        const int oc1 = oc0 + 1;
        const float b00 = s_b[oc0], a00 = s_a[oc0];
        const float b01 = s_b[oc1], a01 = s_a[oc1];
#pragma unroll
        for (int h = 0; h < 2; h++) {
            const int m = mt * 16 + g + 8 * h;
            if (m < 72) {
                const int im = m / 9;
                const int p = m - im * 9;
                const int hh = p / 3;
                const int ww = p - hh * 3;
                float* ob = g_B4 + (size_t)(n0 + im) * 1152 + ww * 384 + hh * 128;
                float v0 = c[nt][2 * h + 0] + b00;
                float v1 = c[nt][2 * h + 1] + b01;
                ob[oc0] = v0 >= 0.f ? v0 : a00 * v0;
                ob[oc1] = v1 >= 0.f ? v1 : a01 * v1;
            }
        }
    }
}

// ---------------------------------------------------------------------------
// K7: fc5 via 3xTF32 mma. Grid (32, 4), 256 thr. Tile 64x64, k-slab 32.
// ---------------------------------------------------------------------------
__global__ __launch_bounds__(256) void k7_fc5(
    const float* __restrict__ W, const float* __restrict__ bias,
    const float* __restrict__ alpha)
{
    __shared__ unsigned sAh[64 * 36], sAl[64 * 36];
    __shared__ unsigned sBh[64 * 36], sBl[64 * 36];

    const int t = threadIdx.x;
    const int bm = blockIdx.x, bn = blockIdx.y;
    const int warp = t >> 5;
    const int lane = t & 31;
    const int g = lane >> 2;
    const int tq = lane & 3;
    const int w_m = warp & 3;
    const int w_n = warp >> 2;

    float c[4][4];
#pragma unroll
    for (int nt = 0; nt < 4; nt++)
#pragma unroll
        for (int qq = 0; qq < 4; qq++) c[nt][qq] = 0.f;

    for (int slab = 0; slab < 36; slab++) {
        const int k0s = slab * 32;
        __syncthreads();
        for (int j = t; j < 512; j += 256) {
            const int m = j >> 3;
            const int kq = (j & 7) * 4;
            float4 v = *(const float4*)(g_B4 + (size_t)(bm * 64 + m) * 1152 + k0s + kq);
            float4 u = *(const float4*)(W + (size_t)(bn * 64 + m) * 1152 + k0s + kq);
            const float va[4] = {v.x, v.y, v.z, v.w};
            const float ua[4] = {u.x, u.y, u.z, u.w};
#pragma unroll
            for (int e = 0; e < 4; e++) {
                unsigned hb = f2tf32(va[e]);
                sAh[m * 36 + kq + e] = hb;
                sAl[m * 36 + kq + e] = f2tf32(va[e] - __uint_as_float(hb));
                unsigned hb2 = f2tf32(ua[e]);
                sBh[m * 36 + kq + e] = hb2;
                sBl[m * 36 + kq + e] = f2tf32(ua[e] - __uint_as_float(hb2));
            }
        }
        __syncthreads();

#pragma unroll
        for (int kt = 0; kt < 4; kt++) {
            const int kk = kt * 8 + tq;
            const int r0 = (w_m * 16 + g) * 36;
            const int r1 = (w_m * 16 + g + 8) * 36;
            const unsigned ah0 = sAh[r0 + kk];
            const unsigned ah1 = sAh[r1 + kk];
            const unsigned ah2 = sAh[r0 + kk + 4];
            const unsigned ah3 = sAh[r1 + kk + 4];
            const unsigned al0 = sAl[r0 + kk];
            const unsigned al1 = sAl[r1 + kk];
            const unsigned al2 = sAl[r0 + kk + 4];
            const unsigned al3 = sAl[r1 + kk + 4];
#pragma unroll
            for (int nt = 0; nt < 4; nt++) {
                const int nr = (w_n * 32 + nt * 8 + g) * 36;
                const unsigned bh0 = sBh[nr + kk];
                const unsigned bh1 = sBh[nr + kk + 4];
                const unsigned bl0 = sBl[nr + kk];
                const unsigned bl1 = sBl[nr + kk + 4];
                mma_tf32(c[nt], ah0, ah1, ah2, ah3, bh0, bh1);
                mma_tf32(c[nt], ah0, ah1, ah2, ah3, bl0, bl1);
                mma_tf32(c[nt], al0, al1, al2, al3, bh0, bh1);
            }
        }
    }

#pragma unroll
    for (int nt = 0; nt < 4; nt++) {
        const int o0 = bn * 64 + w_n * 32 + nt * 8 + 2 * tq;
        const int o1 = o0 + 1;
        const float bi0 = bias[o0], al0 = alpha[o0];
        const float bi1 = bias[o1], al1 = alpha[o1];
#pragma unroll
        for (int h = 0; h < 2; h++) {
            const int m = bm * 64 + w_m * 16 + g + 8 * h;
            float v0 = c[nt][2 * h + 0] + bi0;
            float v1 = c[nt][2 * h + 1] + bi1;
            g_B5[(size_t)m * 256 + o0] = v0 >= 0.f ? v0 : al0 * v0;
            g_B5[(size_t)m * 256 + o1] = v1 >= 0.f ? v1 : al1 * v1;
        }
    }
}

// ---------------------------------------------------------------------------
// K8: heads. One warp per image. out layout: [b: N*4 | c: N*10 | a: N*2]
// ---------------------------------------------------------------------------
__global__ __launch_bounds__(256) void k8_heads(
    const float* __restrict__ w1, const float* __restrict__ b1,
    const float* __restrict__ w2, const float* __restrict__ b2,
    const float* __restrict__ w3, const float* __restrict__ b3,
    float* __restrict__ out)
{
    const int warp = (blockIdx.x * 256 + threadIdx.x) >> 5;
    const int lane = threadIdx.x & 31;
    if (warp >= NIMG) return;
    const float* hv = g_B5 + (size_t)warp * 256;
    float hr[8];
#pragma unroll
    for (int j = 0; j < 8; j++) hr[j] = hv[lane + j * 32];

    auto dot = [&](const float* wrow) {
        float s = 0.f;
#pragma unroll
        for (int j = 0; j < 8; j++) s += hr[j] * wrow[lane + j * 32];
#pragma unroll
        for (int off = 16; off; off >>= 1) s += __shfl_xor_sync(0xffffffffu, s, off);
        return s;
    };

    float* out_b = out;
    float* out_c = out + (size_t)NIMG * 4;
    float* out_a = out + (size_t)NIMG * 14;

    float l0 = dot(w1) + b1[0];
    float l1 = dot(w1 + 256) + b1[1];
    float mx = fmaxf(l0, l1);
    float e0 = expf(l0 - mx), e1 = expf(l1 - mx);
    float inv = 1.f / (e0 + e1);
    if (lane == 0) {
        out_a[warp * 2 + 0] = e0 * inv;
        out_a[warp * 2 + 1] = e1 * inv;
    }
#pragma unroll
    for (int o = 0; o < 4; o++) {
        float v = dot(w2 + o * 256) + b2[o];
        if (lane == 0) out_b[warp * 4 + o] = v;
    }
#pragma unroll
    for (int o = 0; o < 10; o++) {
        float v = dot(w3 + o * 256) + b3[o];
        if (lane == 0) out_c[warp * 10 + o] = v;
    }
}

// ---------------------------------------------------------------------------
extern "C" void kernel_launch(void* const* d_in, const int* in_sizes, int n_in,
                              void* d_out, int out_size)
{
    const float* x    = (const float*)d_in[0];
    const float* c1w  = (const float*)d_in[1];
    const float* c1b  = (const float*)d_in[2];
    const float* a1   = (const float*)d_in[3];
    const float* c2w  = (const float*)d_in[4];
    const float* c2b  = (const float*)d_in[5];
    const float* a2   = (const float*)d_in[6];
    const float* c3w  = (const float*)d_in[7];
    const float* c3b  = (const float*)d_in[8];
    const float* a3   = (const float*)d_in[9];
    const float* c4w  = (const float*)d_in[10];
    const float* c4b  = (const float*)d_in[11];
    const float* a4   = (const float*)d_in[12];
    const float* d5w  = (const float*)d_in[13];
    const float* d5b  = (const float*)d_in[14];
    const float* a5   = (const float*)d_in[15];
    const float* d61w = (const float*)d_in[16];
    const float* d61b = (const float*)d_in[17];
    const float* d62w = (const float*)d_in[18];
    const float* d62b = (const float*)d_in[19];
    const float* d63w = (const float*)d_in[20];
    const float* d63b = (const float*)d_in[21];
    float* out = (float*)d_out;

    cudaFuncSetAttribute(k1_conv1_pool, cudaFuncAttributeMaxDynamicSharedMemorySize,
                         K1_SMEM_FLOATS * 4);
    cudaFuncSetAttribute(k2_conv2_pool, cudaFuncAttributeMaxDynamicSharedMemorySize,
                         K2_SMEM_FLOATS * 4);
    cudaFuncSetAttribute(k4_conv3_pool, cudaFuncAttributeMaxDynamicSharedMemorySize,
                         K4_SMEM_FLOATS * 4);
    cudaFuncSetAttribute(k6_conv4, cudaFuncAttributeMaxDynamicSharedMemorySize,
                         K6_SMEM_FLOATS * 4);

    k1_conv1_pool<<<dim3(NIMG, 4), 288, K1_SMEM_FLOATS * 4>>>(x, c1w, c1b, a1);
    k2_conv2_pool<<<NIMG, 448, K2_SMEM_FLOATS * 4>>>(c2w, c2b, a2);
    k4_conv3_pool<<<NIMG / 4, 256, K4_SMEM_FLOATS * 4>>>(c3w, c3b, a3);
    k6_conv4<<<NIMG / 8, 320, K6_SMEM_FLOATS * 4>>>(c4w, c4b, a4);
    k7_fc5<<<dim3(32, 4), 256>>>(d5w, d5b, a5);
    k8_heads<<<(NIMG * 32) / 256, 256>>>(d61w, d61b, d62w, d62b, d63w, d63b, out);
}

// round 10
// speedup vs baseline: 1.6348x; 1.0981x over previous
#include <cuda_runtime.h>
#include <cuda_bf16.h>
#include <math.h>

// ---------------------------------------------------------------------------
// MTCNN ONet forward, N=2048. Round 10: staging hoist.
//  K0: prep — weights -> tf32 MMA layouts (once per launch)
//  K1: conv1+PReLU+pool fp32 -> g_B1 (tf32 bits, padded [32][23][24])
//  K2: conv2+PReLU+pool TF32 MMA -> g_B2 (tf32 bits, padded [64][10][12])
//  K4: conv3+PReLU+pool TF32 MMA -> g_B3 (tf32 bits [64][16])
//  K6: conv4+PReLU+permute TF32 MMA -> g_B4 (fp32)
//  K7: fc5 3xTF32 MMA -> g_B5
//  K8: heads -> d_out
// ---------------------------------------------------------------------------

#define NIMG 2048

__device__ unsigned g_B1[(size_t)NIMG * 32 * 552];   // tf32 [n][32][23][24]
__device__ unsigned g_B2[(size_t)NIMG * 64 * 120];   // tf32 [n][64][10][12]
__device__ unsigned g_B3[(size_t)NIMG * 64 * 16];    // tf32 [n][64][16]
__device__ float    g_B4[(size_t)NIMG * 1152];
__device__ float    g_B5[(size_t)NIMG * 256];
__device__ unsigned g_W2T[288 * 72];                 // [k][oc pad72]
__device__ unsigned g_W3T[4 * 144 * 72];             // [chunk*144+k][oc pad72]
__device__ unsigned g_W6T[256 * 136];                // [k][oc pad136]

#define NEG_INF (-1e30f)

__device__ __forceinline__ unsigned f2tf32(float f) {
    unsigned u;
    asm("cvt.rna.tf32.f32 %0, %1;" : "=r"(u) : "f"(f));
    return u;
}

__device__ __forceinline__ void mma_tf32(float c[4],
    unsigned a0, unsigned a1, unsigned a2, unsigned a3,
    unsigned b0, unsigned b1)
{
    asm volatile(
        "mma.sync.aligned.m16n8k8.row.col.f32.tf32.tf32.f32 "
        "{%0,%1,%2,%3}, {%4,%5,%6,%7}, {%8,%9}, {%0,%1,%2,%3};"
        : "+f"(c[0]), "+f"(c[1]), "+f"(c[2]), "+f"(c[3])
        : "r"(a0), "r"(a1), "r"(a2), "r"(a3), "r"(b0), "r"(b1));
}

// ---------------------------------------------------------------------------
// K0: weight prep. 18432 (W2) + 36864 (W3) + 32768 (W6) = 88064 elements.
// ---------------------------------------------------------------------------
__global__ __launch_bounds__(256) void k0_prep(
    const float* __restrict__ c2w, const float* __restrict__ c3w,
    const float* __restrict__ c4w)
{
    const int i = blockIdx.x * 256 + threadIdx.x;
    if (i < 18432) {
        const int k = i / 64, oc = i - k * 64;
        g_W2T[k * 72 + oc] = f2tf32(c2w[oc * 288 + k]);
    } else if (i < 18432 + 36864) {
        const int j = i - 18432;
        const int row = j / 64, oc = j - row * 64;     // row = chunk*144+k
        const int chunk = row / 144, k = row - chunk * 144;
        g_W3T[row * 72 + oc] = f2tf32(c3w[oc * 576 + chunk * 144 + k]);
    } else if (i < 88064) {
        const int j = i - 55296;
        const int k = j >> 7, oc = j & 127;
        g_W6T[k * 136 + oc] = f2tf32(c4w[oc * 256 + k]);
    }
}

// ---------------------------------------------------------------------------
// K1: conv1 + PReLU + pool1 (fp32). Grid (NIMG, 4), 288 thr, 2 CTAs/SM.
// Writes g_B1 as tf32 bits in padded [32][23][24] layout.
// ---------------------------------------------------------------------------
#define K1_SMEM_FLOATS (6912 + 16928 + 216 + 8 + 8)
__global__ __launch_bounds__(288, 2) void k1_conv1_pool(
    const float* __restrict__ x, const float* __restrict__ w,
    const float* __restrict__ bias, const float* __restrict__ alpha)
{
    extern __shared__ float sm1[];
    float* s_in = sm1;            // 3*48*48
    float* s_cv = sm1 + 6912;     // 8*46*46
    float* s_w  = s_cv + 16928;   // 8*27
    float* s_b  = s_w + 216;
    float* s_a  = s_b + 8;

    const int n = blockIdx.x;
    const int ocg = blockIdx.y;
    const int tid = threadIdx.x;
    {
        const float4* src = (const float4*)(x + (size_t)n * 6912);
        float4* dst = (float4*)s_in;
        for (int i = tid; i < 6912 / 4; i += 288) dst[i] = src[i];
        if (tid < 216) s_w[tid] = w[ocg * 216 + tid];
        if (tid < 8) {
            s_b[tid] = bias[ocg * 8 + tid];
            s_a[tid] = alpha[ocg * 8 + tid];
        }
    }
    __syncthreads();

    if (tid < 276) {
        const int y = tid / 6;
        const int xg = (tid % 6) * 8;

        float acc[8][8];
#pragma unroll
        for (int o = 0; o < 8; o++)
#pragma unroll
            for (int j = 0; j < 8; j++) acc[o][j] = 0.f;

#pragma unroll
        for (int ic = 0; ic < 3; ic++) {
#pragma unroll
            for (int ky = 0; ky < 3; ky++) {
                const float* row = s_in + ic * 2304 + (y + ky) * 48;
                float xi[10];
#pragma unroll
                for (int j = 0; j < 10; j++) {
                    int c = xg + j;
                    xi[j] = row[c > 47 ? 47 : c];
                }
#pragma unroll
                for (int o = 0; o < 8; o++) {
                    const float* wp = s_w + o * 27 + ic * 9 + ky * 3;
                    float w0 = wp[0], w1 = wp[1], w2 = wp[2];
#pragma unroll
                    for (int j = 0; j < 8; j++)
                        acc[o][j] += xi[j] * w0 + xi[j + 1] * w1 + xi[j + 2] * w2;
                }
            }
        }
#pragma unroll
        for (int o = 0; o < 8; o++) {
            const float b0 = s_b[o], al = s_a[o];
            float* orow = s_cv + o * 2116 + y * 46;
#pragma unroll
            for (int j = 0; j < 8; j++) {
                const int xx = xg + j;
                if (xx < 46) {
                    float v = acc[o][j] + b0;
                    orow[xx] = v >= 0.f ? v : al * v;
                }
            }
        }
    }
    __syncthreads();

    // pool -> g_B1 tf32 [n][32][py][24]
    unsigned* ob = g_B1 + (size_t)n * 17664 + (size_t)ocg * 8 * 552;
    for (int i = tid; i < 8 * 529; i += 288) {
        const int o = i / 529;
        const int rem = i % 529;
        const int py = rem / 23;
        const int px = rem % 23;
        const float* base = s_cv + o * 2116;
        float m = NEG_INF;
#pragma unroll
        for (int ky = 0; ky < 3; ky++) {
            int cy = py * 2 + ky; cy = cy > 45 ? 45 : cy;
#pragma unroll
            for (int kx = 0; kx < 3; kx++) {
                int cx = px * 2 + kx; cx = cx > 45 ? 45 : cx;
                m = fmaxf(m, base[cy * 46 + cx]);
            }
        }
        ob[o * 552 + py * 24 + px] = f2tf32(m);
    }
}

// ---------------------------------------------------------------------------
// K2: conv2 + PReLU + pool2 via TF32 mma. One image/block, 448 threads.
// Input + weights staged by pure uint4 copy from prepped buffers.
// ---------------------------------------------------------------------------
#define K2_STW 72
#define K2_SIN_SZ 17728
#define K2_SW_OFF K2_SIN_SZ
#define K2_SW_SZ (288 * K2_STW)
#define K2_OFF_OFF (K2_SW_OFF + K2_SW_SZ)
#define K2_B_OFF (K2_OFF_OFF + 288)
#define K2_A_OFF (K2_B_OFF + 64)
#define K2_SMEM_FLOATS (K2_A_OFF + 64)
#define K2_CV_STRIDE 448

__global__ __launch_bounds__(448, 1) void k2_conv2_pool(
    const float* __restrict__ bias, const float* __restrict__ alpha)
{
    extern __shared__ float sm2[];
    float* s_in = sm2;
    float* s_w  = sm2 + K2_SW_OFF;
    int*   s_off = (int*)(sm2 + K2_OFF_OFF);
    float* s_b  = sm2 + K2_B_OFF;
    float* s_a  = sm2 + K2_A_OFF;
    float* s_cv = sm2;

    const int n = blockIdx.x;
    const int t = threadIdx.x;

    {
        const uint4* src = (const uint4*)(g_B1 + (size_t)n * 17664);
        uint4* dst = (uint4*)s_in;
        for (int i = t; i < 4416; i += 448) dst[i] = src[i];
        const uint4* ws = (const uint4*)g_W2T;
        uint4* wd = (uint4*)s_w;
        for (int i = t; i < 5184; i += 448) wd[i] = ws[i];
        if (t < 288) {
            const int k = t;
            const int ic = k / 9;
            const int r = k - ic * 9;
            s_off[k] = ic * 552 + (r / 3) * 24 + (r % 3);
        }
        if (t < 64) {
            s_b[t] = bias[t];
            s_a[t] = alpha[t];
        }
    }
    __syncthreads();

    const int warp = t >> 5;
    const int lane = t & 31;
    const int g = lane >> 2;
    const int tq = lane & 3;

    int rb[2][2];
    int mrow[2][2];
#pragma unroll
    for (int mi = 0; mi < 2; mi++) {
        const int mt = 2 * warp + mi;
        int m0 = mt * 16 + g;
        int m1 = m0 + 8;
        mrow[mi][0] = m0; mrow[mi][1] = m1;
        int c0 = m0 > 440 ? 440 : m0;
        int c1 = m1 > 440 ? 440 : m1;
        rb[mi][0] = (c0 / 21) * 24 + (c0 % 21);
        rb[mi][1] = (c1 / 21) * 24 + (c1 % 21);
    }

    float c[2][8][4];
#pragma unroll
    for (int mi = 0; mi < 2; mi++)
#pragma unroll
        for (int nt = 0; nt < 8; nt++)
#pragma unroll
            for (int qq = 0; qq < 4; qq++) c[mi][nt][qq] = 0.f;

    const unsigned* u_in = (const unsigned*)s_in;
    const unsigned* u_w = (const unsigned*)s_w;

    for (int kt = 0; kt < 36; kt++) {
        const int k0 = kt * 8 + tq;
        const int off0 = s_off[k0];
        const int off1 = s_off[k0 + 4];

        unsigned b0[8], b1[8];
        const unsigned* wb = u_w + k0 * K2_STW + g;
#pragma unroll
        for (int nt = 0; nt < 8; nt++) {
            b0[nt] = wb[nt * 8];
            b1[nt] = wb[4 * K2_STW + nt * 8];
        }
#pragma unroll
        for (int mi = 0; mi < 2; mi++) {
            const unsigned a0 = u_in[rb[mi][0] + off0];
            const unsigned a1 = u_in[rb[mi][1] + off0];
            const unsigned a2 = u_in[rb[mi][0] + off1];
            const unsigned a3 = u_in[rb[mi][1] + off1];
#pragma unroll
            for (int nt = 0; nt < 8; nt++)
                mma_tf32(c[mi][nt], a0, a1, a2, a3, b0[nt], b1[nt]);
        }
    }
    __syncthreads();

#pragma unroll
    for (int mi = 0; mi < 2; mi++) {
#pragma unroll
        for (int nt = 0; nt < 8; nt++) {
            const int oc0 = nt * 8 + 2 * tq;
            const int oc1 = oc0 + 1;
            const float b00 = s_b[oc0], a00 = s_a[oc0];
            const float b01 = s_b[oc1], a01 = s_a[oc1];
#pragma unroll
            for (int h = 0; h < 2; h++) {
                const int m = mrow[mi][h];
                if (m < 441) {
                    float v0 = c[mi][nt][2 * h + 0] + b00;
                    float v1 = c[mi][nt][2 * h + 1] + b01;
                    s_cv[oc0 * K2_CV_STRIDE + m] = v0 >= 0.f ? v0 : a00 * v0;
                    s_cv[oc1 * K2_CV_STRIDE + m] = v1 >= 0.f ? v1 : a01 * v1;
                }
            }
        }
    }
    __syncthreads();

    // pool -> g_B2 tf32 [n][64][py][12]
    unsigned* ob = g_B2 + (size_t)n * 7680;
    for (int i = t; i < 6400; i += 448) {
        const int oc = i / 100;
        const int r = i - oc * 100;
        const int py = r / 10;
        const int px = r - py * 10;
        const float* base = s_cv + oc * K2_CV_STRIDE + (py * 2) * 21 + px * 2;
        float m = NEG_INF;
#pragma unroll
        for (int ky = 0; ky < 3; ky++)
#pragma unroll
            for (int kx = 0; kx < 3; kx++)
                m = fmaxf(m, base[ky * 21 + kx]);
        ob[oc * 120 + py * 12 + px] = f2tf32(m);
    }
}

// ---------------------------------------------------------------------------
// K4: conv3 + PReLU + pool3 via single TF32 mma. 4 img/block, 256 thr.
// Staging = uint4 copies from padded g_B2 and prepped W3T.
// ---------------------------------------------------------------------------
#define K4_INH 0
#define K4_WH 7680
#define K4_OFFT 18048
#define K4_BO 18192
#define K4_AO 18256
#define K4_SMEM_FLOATS 18320

__global__ __launch_bounds__(256) void k4_conv3_pool(
    const float* __restrict__ bias, const float* __restrict__ alpha)
{
    extern __shared__ float sm4[];
    unsigned* inh = (unsigned*)(sm4 + K4_INH);   // [4img][16ic][10][12]
    unsigned* wh  = (unsigned*)(sm4 + K4_WH);    // [144][72]
    int* s_off    = (int*)(sm4 + K4_OFFT);
    float* s_b    = sm4 + K4_BO;
    float* s_a    = sm4 + K4_AO;
    float* s_cv   = sm4;                         // overlay [4][64][64] = 16384

    const int n0 = blockIdx.x * 4;
    const int t = threadIdx.x;
    const int warp = t >> 5;
    const int lane = t & 31;
    const int g = lane >> 2;
    const int tq = lane & 3;

    if (t < 64) {
        s_b[t] = bias[t];
        s_a[t] = alpha[t];
    }
    if (t < 144) {
        const int ic = t / 9;
        const int r = t - ic * 9;
        s_off[t] = ic * 120 + (r / 3) * 12 + (r % 3);
    }

    int rb[2][2];
#pragma unroll
    for (int mi = 0; mi < 2; mi++) {
        const int mt = 2 * warp + mi;
#pragma unroll
        for (int h = 0; h < 2; h++) {
            const int m = mt * 16 + g + 8 * h;
            const int img = m >> 6;
            const int px = m & 63;
            rb[mi][h] = img * 1920 + (px >> 3) * 12 + (px & 7);
        }
    }

    float c[2][8][4];
#pragma unroll
    for (int mi = 0; mi < 2; mi++)
#pragma unroll
        for (int nt = 0; nt < 8; nt++)
#pragma unroll
            for (int qq = 0; qq < 4; qq++) c[mi][nt][qq] = 0.f;

    for (int chunk = 0; chunk < 4; chunk++) {
        __syncthreads();
        {
            uint4* dst = (uint4*)inh;
            for (int i = t; i < 1920; i += 256) {
                const int im = i / 480, rem = i - im * 480;
                dst[im * 480 + rem] = ((const uint4*)g_B2)[
                    (size_t)(n0 + im) * 1920 + chunk * 480 + rem];
            }
            const uint4* ws = (const uint4*)g_W3T + chunk * 2592;
            uint4* wd = (uint4*)wh;
            for (int i = t; i < 2592; i += 256) wd[i] = ws[i];
        }
        __syncthreads();

        for (int kt = 0; kt < 18; kt++) {
            const int k0 = kt * 8 + tq;
            const int off0 = s_off[k0];
            const int off1 = s_off[k0 + 4];

            unsigned b0[8], b1[8];
            const unsigned* wb = wh + k0 * 72 + g;
#pragma unroll
            for (int nt = 0; nt < 8; nt++) {
                b0[nt] = wb[nt * 8];
                b1[nt] = wb[4 * 72 + nt * 8];
            }
#pragma unroll
            for (int mi = 0; mi < 2; mi++) {
                const unsigned a0 = inh[rb[mi][0] + off0];
                const unsigned a1 = inh[rb[mi][1] + off0];
                const unsigned a2 = inh[rb[mi][0] + off1];
                const unsigned a3 = inh[rb[mi][1] + off1];
#pragma unroll
                for (int nt = 0; nt < 8; nt++)
                    mma_tf32(c[mi][nt], a0, a1, a2, a3, b0[nt], b1[nt]);
            }
        }
    }
    __syncthreads();

#pragma unroll
    for (int mi = 0; mi < 2; mi++) {
        const int mt = 2 * warp + mi;
#pragma unroll
        for (int nt = 0; nt < 8; nt++) {
            const int oc0 = nt * 8 + 2 * tq;
            const int oc1 = oc0 + 1;
            const float b00 = s_b[oc0], a00 = s_a[oc0];
            const float b01 = s_b[oc1], a01 = s_a[oc1];
#pragma unroll
            for (int h = 0; h < 2; h++) {
                const int m = mt * 16 + g + 8 * h;
                const int img = m >> 6;
                const int px = m & 63;
                float v0 = c[mi][nt][2 * h + 0] + b00;
                float v1 = c[mi][nt][2 * h + 1] + b01;
                s_cv[(img * 64 + oc0) * 64 + px] = v0 >= 0.f ? v0 : a00 * v0;
                s_cv[(img * 64 + oc1) * 64 + px] = v1 >= 0.f ? v1 : a01 * v1;
            }
        }
    }
    __syncthreads();

    for (int i = t; i < 4096; i += 256) {
        const int img = i >> 10;
        const int rem = i & 1023;
        const int oc = rem >> 4;
        const int p = rem & 15;
        const int py = p >> 2;
        const int px = p & 3;
        const float* base = s_cv + (img * 64 + oc) * 64 + py * 16 + px * 2;
        float m = fmaxf(fmaxf(base[0], base[1]), fmaxf(base[8], base[9]));
        g_B3[((size_t)(n0 + img) * 64 + oc) * 16 + p] = f2tf32(m);
    }
}

// ---------------------------------------------------------------------------
// K6: conv4 (64->128,2x2)+PReLU+permute flatten via TF32 mma.
// 8 img/block, 320 threads. Staging = uint4 copies (g_B3 tf32, W6T).
// ---------------------------------------------------------------------------
#define K6_IN 0
#define K6_W 4096
#define K6_OFF 21504
#define K6_B 21632
#define K6_A 21760
#define K6_SMEM_FLOATS 21888

__global__ __launch_bounds__(320) void k6_conv4(
    const float* __restrict__ bias, const float* __restrict__ alpha)
{
    extern __shared__ float sm6[];
    unsigned* u_in = (unsigned*)(sm6 + K6_IN);   // [8][32][16]
    unsigned* u_w  = (unsigned*)(sm6 + K6_W);    // [128][136]
    int* s_off     = (int*)(sm6 + K6_OFF);
    float* s_b     = sm6 + K6_B;
    float* s_a     = sm6 + K6_A;

    const int n0 = blockIdx.x * 8;
    const int t = threadIdx.x;
    const int warp = t >> 5;
    const int lane = t & 31;
    const int g = lane >> 2;
    const int tq = lane & 3;
    const int mt = warp >> 1;
    const int nh = warp & 1;

    if (t < 128) {
        const int k = t;
        const int icl = k >> 2;
        const int ky = (k >> 1) & 1;
        const int kx = k & 1;
        s_off[k] = icl * 16 + ky * 4 + kx;
        s_b[t] = bias[t];
        s_a[t] = alpha[t];
    }

    int rb[2];
#pragma unroll
    for (int h = 0; h < 2; h++) {
        int m = mt * 16 + g + 8 * h;
        if (m > 71) m = 71;
        const int im = m / 9;
        const int p = m - im * 9;
        rb[h] = im * 512 + (p / 3) * 4 + (p % 3);
    }

    float c[8][4];
#pragma unroll
    for (int nt = 0; nt < 8; nt++)
#pragma unroll
        for (int qq = 0; qq < 4; qq++) c[nt][qq] = 0.f;

    for (int chunk = 0; chunk < 2; chunk++) {
        __syncthreads();
        {
            uint4* dst = (uint4*)u_in;
            for (int i = t; i < 1024; i += 320) {
                const int im = i >> 7, rem = i & 127;
                dst[i] = ((const uint4*)g_B3)[
                    (size_t)(n0 + im) * 256 + chunk * 128 + rem];
            }
            const uint4* ws = (const uint4*)g_W6T + chunk * 4352;
            uint4* wd = (uint4*)u_w;
            for (int i = t; i < 4352; i += 320) wd[i] = ws[i];
        }
        __syncthreads();

        for (int kt = 0; kt < 16; kt++) {
            const int k0 = kt * 8 + tq;
            const int off0 = s_off[k0];
            const int off1 = s_off[k0 + 4];

            unsigned b0[8], b1[8];
            const unsigned* wb = u_w + k0 * 136 + nh * 64 + g;
#pragma unroll
            for (int nt = 0; nt < 8; nt++) {
                b0[nt] = wb[nt * 8];
                b1[nt] = wb[4 * 136 + nt * 8];
            }
            const unsigned a0 = u_in[rb[0] + off0];
            const unsigned a1 = u_in[rb[1] + off0];
            const unsigned a2 = u_in[rb[0] + off1];
            const unsigned a3 = u_in[rb[1] + off1];
#pragma unroll
            for (int nt = 0; nt < 8; nt++)
                mma_tf32(c[nt], a0, a1, a2, a3, b0[nt], b1[nt]);
        }
    }

#pragma unroll
    for (int nt = 0; nt < 8; nt++) {
        const int oc0 = nh * 64 + nt * 8 + 2 * tq;
        const int oc1 = oc0 + 1;
        const float b00 = s_b[oc0], a00 = s_a[oc0];
        const float b01 = s_b[oc1], a01 = s_a[oc1];
#pragma unroll
        for (int h = 0; h < 2; h++) {
            const int m = mt * 16 + g + 8 * h;
            if (m < 72) {
                const int im = m / 9;
                const int p = m - im * 9;
                const int hh = p / 3;
                const int ww = p - hh * 3;
                float* ob = g_B4 + (size_t)(n0 + im) * 1152 + ww * 384 + hh * 128;
                float v0 = c[nt][2 * h + 0] + b00;
                float v1 = c[nt][2 * h + 1] + b01;
                ob[oc0] = v0 >= 0.f ? v0 : a00 * v0;
                ob[oc1] = v1 >= 0.f ? v1 : a01 * v1;
            }
        }
    }
}

// ---------------------------------------------------------------------------
// K7: fc5 via 3xTF32 mma. Grid (32, 4), 256 thr. Tile 64x64, k-slab 32.
// ---------------------------------------------------------------------------
__global__ __launch_bounds__(256) void k7_fc5(
    const float* __restrict__ W, const float* __restrict__ bias,
    const float* __restrict__ alpha)
{
    __shared__ unsigned sAh[64 * 36], sAl[64 * 36];
    __shared__ unsigned sBh[64 * 36], sBl[64 * 36];

    const int t = threadIdx.x;
    const int bm = blockIdx.x, bn = blockIdx.y;
    const int warp = t >> 5;
    const int lane = t & 31;
    const int g = lane >> 2;
    const int tq = lane & 3;
    const int w_m = warp & 3;
    const int w_n = warp >> 2;

    float c[4][4];
#pragma unroll
    for (int nt = 0; nt < 4; nt++)
#pragma unroll
        for (int qq = 0; qq < 4; qq++) c[nt][qq] = 0.f;

    for (int slab = 0; slab < 36; slab++) {
        const int k0s = slab * 32;
        __syncthreads();
        for (int j = t; j < 512; j += 256) {
            const int m = j >> 3;
            const int kq = (j & 7) * 4;
            float4 v = *(const float4*)(g_B4 + (size_t)(bm * 64 + m) * 1152 + k0s + kq);
            float4 u = *(const float4*)(W + (size_t)(bn * 64 + m) * 1152 + k0s + kq);
            const float va[4] = {v.x, v.y, v.z, v.w};
            const float ua[4] = {u.x, u.y, u.z, u.w};
#pragma unroll
            for (int e = 0; e < 4; e++) {
                unsigned hb = f2tf32(va[e]);
                sAh[m * 36 + kq + e] = hb;
                sAl[m * 36 + kq + e] = f2tf32(va[e] - __uint_as_float(hb));
                unsigned hb2 = f2tf32(ua[e]);
                sBh[m * 36 + kq + e] = hb2;
                sBl[m * 36 + kq + e] = f2tf32(ua[e] - __uint_as_float(hb2));
            }
        }
        __syncthreads();

#pragma unroll
        for (int kt = 0; kt < 4; kt++) {
            const int kk = kt * 8 + tq;
            const int r0 = (w_m * 16 + g) * 36;
            const int r1 = (w_m * 16 + g + 8) * 36;
            const unsigned ah0 = sAh[r0 + kk];
            const unsigned ah1 = sAh[r1 + kk];
            const unsigned ah2 = sAh[r0 + kk + 4];
            const unsigned ah3 = sAh[r1 + kk + 4];
            const unsigned al0 = sAl[r0 + kk];
            const unsigned al1 = sAl[r1 + kk];
            const unsigned al2 = sAl[r0 + kk + 4];
            const unsigned al3 = sAl[r1 + kk + 4];
#pragma unroll
            for (int nt = 0; nt < 4; nt++) {
                const int nr = (w_n * 32 + nt * 8 + g) * 36;
                const unsigned bh0 = sBh[nr + kk];
                const unsigned bh1 = sBh[nr + kk + 4];
                const unsigned bl0 = sBl[nr + kk];
                const unsigned bl1 = sBl[nr + kk + 4];
                mma_tf32(c[nt], ah0, ah1, ah2, ah3, bh0, bh1);
                mma_tf32(c[nt], ah0, ah1, ah2, ah3, bl0, bl1);
                mma_tf32(c[nt], al0, al1, al2, al3, bh0, bh1);
            }
        }
    }

#pragma unroll
    for (int nt = 0; nt < 4; nt++) {
        const int o0 = bn * 64 + w_n * 32 + nt * 8 + 2 * tq;
        const int o1 = o0 + 1;
        const float bi0 = bias[o0], al0 = alpha[o0];
        const float bi1 = bias[o1], al1 = alpha[o1];
#pragma unroll
        for (int h = 0; h < 2; h++) {
            const int m = bm * 64 + w_m * 16 + g + 8 * h;
            float v0 = c[nt][2 * h + 0] + bi0;
            float v1 = c[nt][2 * h + 1] + bi1;
            g_B5[(size_t)m * 256 + o0] = v0 >= 0.f ? v0 : al0 * v0;
            g_B5[(size_t)m * 256 + o1] = v1 >= 0.f ? v1 : al1 * v1;
        }
    }
}

// ---------------------------------------------------------------------------
// K8: heads. One warp per image. out layout: [b: N*4 | c: N*10 | a: N*2]
// ---------------------------------------------------------------------------
__global__ __launch_bounds__(256) void k8_heads(
    const float* __restrict__ w1, const float* __restrict__ b1,
    const float* __restrict__ w2, const float* __restrict__ b2,
    const float* __restrict__ w3, const float* __restrict__ b3,
    float* __restrict__ out)
{
    const int warp = (blockIdx.x * 256 + threadIdx.x) >> 5;
    const int lane = threadIdx.x & 31;
    if (warp >= NIMG) return;
    const float* hv = g_B5 + (size_t)warp * 256;
    float hr[8];
#pragma unroll
    for (int j = 0; j < 8; j++) hr[j] = hv[lane + j * 32];

    auto dot = [&](const float* wrow) {
        float s = 0.f;
#pragma unroll
        for (int j = 0; j < 8; j++) s += hr[j] * wrow[lane + j * 32];
#pragma unroll
        for (int off = 16; off; off >>= 1) s += __shfl_xor_sync(0xffffffffu, s, off);
        return s;
    };

    float* out_b = out;
    float* out_c = out + (size_t)NIMG * 4;
    float* out_a = out + (size_t)NIMG * 14;

    float l0 = dot(w1) + b1[0];
    float l1 = dot(w1 + 256) + b1[1];
    float mx = fmaxf(l0, l1);
    float e0 = expf(l0 - mx), e1 = expf(l1 - mx);
    float inv = 1.f / (e0 + e1);
    if (lane == 0) {
        out_a[warp * 2 + 0] = e0 * inv;
        out_a[warp * 2 + 1] = e1 * inv;
    }
#pragma unroll
    for (int o = 0; o < 4; o++) {
        float v = dot(w2 + o * 256) + b2[o];
        if (lane == 0) out_b[warp * 4 + o] = v;
    }
#pragma unroll
    for (int o = 0; o < 10; o++) {
        float v = dot(w3 + o * 256) + b3[o];
        if (lane == 0) out_c[warp * 10 + o] = v;
    }
}

// ---------------------------------------------------------------------------
extern "C" void kernel_launch(void* const* d_in, const int* in_sizes, int n_in,
                              void* d_out, int out_size)
{
    const float* x    = (const float*)d_in[0];
    const float* c1w  = (const float*)d_in[1];
    const float* c1b  = (const float*)d_in[2];
    const float* a1   = (const float*)d_in[3];
    const float* c2w  = (const float*)d_in[4];
    const float* c2b  = (const float*)d_in[5];
    const float* a2   = (const float*)d_in[6];
    const float* c3w  = (const float*)d_in[7];
    const float* c3b  = (const float*)d_in[8];
    const float* a3   = (const float*)d_in[9];
    const float* c4w  = (const float*)d_in[10];
    const float* c4b  = (const float*)d_in[11];
    const float* a4   = (const float*)d_in[12];
    const float* d5w  = (const float*)d_in[13];
    const float* d5b  = (const float*)d_in[14];
    const float* a5   = (const float*)d_in[15];
    const float* d61w = (const float*)d_in[16];
    const float* d61b = (const float*)d_in[17];
    const float* d62w = (const float*)d_in[18];
    const float* d62b = (const float*)d_in[19];
    const float* d63w = (const float*)d_in[20];
    const float* d63b = (const float*)d_in[21];
    float* out = (float*)d_out;

    cudaFuncSetAttribute(k1_conv1_pool, cudaFuncAttributeMaxDynamicSharedMemorySize,
                         K1_SMEM_FLOATS * 4);
    cudaFuncSetAttribute(k2_conv2_pool, cudaFuncAttributeMaxDynamicSharedMemorySize,
                         K2_SMEM_FLOATS * 4);
    cudaFuncSetAttribute(k4_conv3_pool, cudaFuncAttributeMaxDynamicSharedMemorySize,
                         K4_SMEM_FLOATS * 4);
    cudaFuncSetAttribute(k6_conv4, cudaFuncAttributeMaxDynamicSharedMemorySize,
                         K6_SMEM_FLOATS * 4);

    k0_prep<<<(88064 + 255) / 256, 256>>>(c2w, c3w, c4w);
    k1_conv1_pool<<<dim3(NIMG, 4), 288, K1_SMEM_FLOATS * 4>>>(x, c1w, c1b, a1);
    k2_conv2_pool<<<NIMG, 448, K2_SMEM_FLOATS * 4>>>(c2b, a2);
    k4_conv3_pool<<<NIMG / 4, 256, K4_SMEM_FLOATS * 4>>>(c3b, a3);
    k6_conv4<<<NIMG / 8, 320, K6_SMEM_FLOATS * 4>>>(c4b, a4);
    k7_fc5<<<dim3(32, 4), 256>>>(d5w, d5b, a5);
    k8_heads<<<(NIMG * 32) / 256, 256>>>(d61w, d61b, d62w, d62b, d63w, d63b, out);
}